// round 1
// baseline (speedup 1.0000x reference)
#include <cuda_runtime.h>
#include <cuda_bf16.h>

// Problem: VQ quantize. x: [32,64,64,64] f32, embed: [64,512] f32.
// Outputs packed f32: quantize (8388608) | diff (1) | embed_ind (131072).

#define DIMK 64
#define NCODE 512
#define NROWS (32 * 64 * 64)            // 131072
#define NTOT (NROWS * DIMK)             // 8388608
#define TPB 256
#define NBLK (NROWS / TPB)              // 512

__device__ float g_partials[NBLK];

typedef unsigned long long ull;

__device__ __forceinline__ ull pack2(float a, float b) {
    return (ull)__float_as_uint(a) | ((ull)__float_as_uint(b) << 32);
}
__device__ __forceinline__ float lo2(ull a) { return __uint_as_float((unsigned)(a & 0xffffffffull)); }
__device__ __forceinline__ float hi2(ull a) { return __uint_as_float((unsigned)(a >> 32)); }

__device__ __forceinline__ void fma2(ull& acc, ull a, ull b) {
    asm("fma.rn.f32x2 %0, %1, %2, %3;" : "=l"(acc) : "l"(a), "l"(b), "l"(acc));
}

// smem: embT [512][64] floats (codebook transposed), then eNorm[512]
__global__ __launch_bounds__(TPB, 1)
void vq_main_kernel(const float* __restrict__ x,
                    const float* __restrict__ embed,
                    float* __restrict__ out,
                    int out_size) {
    extern __shared__ float smem[];
    float* embT = smem;                  // [k*64 + d]
    float* eNorm = smem + NCODE * DIMK;  // [k]
    int tid = threadIdx.x;

    // Load codebook transposed: embed[d*512+k] -> embT[k*64+d]
    for (int i = tid; i < NCODE * DIMK; i += TPB) {
        int d = i >> 9;       // / 512
        int k = i & 511;
        embT[k * DIMK + d] = embed[i];
    }
    // Code norms (coalesced global reads; one-time)
    for (int k = tid; k < NCODE; k += TPB) {
        float s = 0.f;
#pragma unroll
        for (int d = 0; d < DIMK; d++) {
            float v = embed[d * NCODE + k];
            s = fmaf(v, v, s);
        }
        eNorm[k] = s;
    }
    __syncthreads();

    // Each thread owns one row, pre-scaled by -2 and packed into f32x2 regs.
    int n = blockIdx.x * TPB + tid;
    const float4* xr4 = (const float4*)(x + (size_t)n * DIMK);
    ull xp[DIMK / 2];
#pragma unroll
    for (int i = 0; i < DIMK / 4; i++) {
        float4 v = xr4[i];
        xp[2 * i + 0] = pack2(-2.f * v.x, -2.f * v.y);
        xp[2 * i + 1] = pack2(-2.f * v.z, -2.f * v.w);
    }

    float best = __int_as_float(0x7f800000);  // +inf
    int bi = 0;
#pragma unroll 1
    for (int k = 0; k < NCODE; k++) {
        const ulonglong2* e = (const ulonglong2*)(embT + k * DIMK);
        ull a0 = 0, a1 = 0, a2 = 0, a3 = 0;
#pragma unroll
        for (int j = 0; j < 16; j += 2) {
            ulonglong2 ev0 = e[j];
            ulonglong2 ev1 = e[j + 1];
            fma2(a0, xp[2 * j + 0], ev0.x);
            fma2(a1, xp[2 * j + 1], ev0.y);
            fma2(a2, xp[2 * j + 2], ev1.x);
            fma2(a3, xp[2 * j + 3], ev1.y);
        }
        float dot = ((lo2(a0) + hi2(a0)) + (lo2(a1) + hi2(a1)))
                  + ((lo2(a2) + hi2(a2)) + (lo2(a3) + hi2(a3)));
        float s = eNorm[k] + dot;  // = ||e_k||^2 - 2 x.e_k   (argmin-equivalent)
        if (s < best) { best = s; bi = k; }
    }

    // Phase 2: cooperative, coalesced row writes + diff partial.
    int lane = tid & 31;
    int wbase = n - lane;
    float dsum = 0.f;
#pragma unroll 1
    for (int r = 0; r < 32; r++) {
        int bk = __shfl_sync(0xffffffffu, bi, r);
        float2 ev = ((const float2*)(embT + bk * DIMK))[lane];
        int rn = wbase + r;
        float2 xv = ((const float2*)(x + (size_t)rn * DIMK))[lane];
        ((float2*)(out + (size_t)rn * DIMK))[lane] = ev;
        float dx = ev.x - xv.x;
        float dy = ev.y - xv.y;
        dsum = fmaf(dx, dx, dsum);
        dsum = fmaf(dy, dy, dsum);
    }

    // embed_ind as float, if the output buffer carries it
    if (out_size >= NTOT + 1 + NROWS) {
        out[NTOT + 1 + n] = (float)bi;
    }

    // Deterministic per-block reduction of dsum
    __shared__ float red[TPB];
    red[tid] = dsum;
    __syncthreads();
#pragma unroll
    for (int s = TPB / 2; s > 0; s >>= 1) {
        if (tid < s) red[tid] += red[tid + s];
        __syncthreads();
    }
    if (tid == 0) g_partials[blockIdx.x] = red[0];
}

__global__ void vq_diff_reduce_kernel(float* __restrict__ out, int out_size) {
    __shared__ float red[NBLK];
    int tid = threadIdx.x;
    red[tid] = g_partials[tid];
    __syncthreads();
#pragma unroll
    for (int s = NBLK / 2; s > 0; s >>= 1) {
        if (tid < s) red[tid] += red[tid + s];
        __syncthreads();
    }
    if (tid == 0 && out_size >= NTOT + 1) {
        out[NTOT] = red[0] * (1.0f / (float)NTOT);
    }
}

extern "C" void kernel_launch(void* const* d_in, const int* in_sizes, int n_in,
                              void* d_out, int out_size) {
    const float* x = (const float*)d_in[0];
    const float* embed = (const float*)d_in[1];
    float* out = (float*)d_out;

    int smem_bytes = (NCODE * DIMK + NCODE) * (int)sizeof(float);  // 133120
    cudaFuncSetAttribute(vq_main_kernel,
                         cudaFuncAttributeMaxDynamicSharedMemorySize, smem_bytes);

    vq_main_kernel<<<NBLK, TPB, smem_bytes>>>(x, embed, out, out_size);
    vq_diff_reduce_kernel<<<1, NBLK>>>(out, out_size);
}

// round 2
// speedup vs baseline: 1.2068x; 1.2068x over previous
#include <cuda_runtime.h>

// VQ quantize. x: [32,64,64,64] f32, embed: [64,512] f32.
// Output f32 packed: quantize (8388608) | diff (1) | embed_ind (131072).

#define DIMK 64
#define NCODE 512
#define NROWS (32 * 64 * 64)            // 131072
#define NTOT (NROWS * DIMK)             // 8388608
#define TPB 512
#define NBLK (NROWS / TPB)              // 256

__device__ unsigned long long g_diff_acc;  // zero-init; kernel restores to 0
__device__ unsigned int g_ticket;          // zero-init; kernel restores to 0

typedef unsigned long long ull;

__device__ __forceinline__ ull pack2(float a, float b) {
    ull r;
    asm("mov.b64 %0, {%1, %2};" : "=l"(r) : "f"(a), "f"(b));
    return r;
}
__device__ __forceinline__ float lo2(ull a) { return __uint_as_float((unsigned)(a & 0xffffffffull)); }
__device__ __forceinline__ float hi2(ull a) { return __uint_as_float((unsigned)(a >> 32)); }

__device__ __forceinline__ void fma2(ull& acc, ull a, ull b) {
    asm("fma.rn.f32x2 %0, %1, %2, %3;" : "=l"(acc) : "l"(a), "l"(b), "l"(acc));
}
__device__ __forceinline__ void add2(ull& d, ull a, ull b) {
    asm("add.rn.f32x2 %0, %1, %2;" : "=l"(d) : "l"(a), "l"(b));
}

// smem: embT [512][64] floats (codebook transposed), then eNorm[512]
__global__ __launch_bounds__(TPB, 1)
void vq_kernel(const float* __restrict__ x,
               const float* __restrict__ embed,
               float* __restrict__ out,
               int out_size) {
    extern __shared__ float smem[];
    float* embT = smem;                  // [k*64 + d]
    float* eNorm = smem + NCODE * DIMK;  // [k]
    int tid = threadIdx.x;

    // Load codebook transposed: embed[d*512+k] -> embT[k*64+d] (coalesced gmem)
    for (int i = tid; i < NCODE * DIMK; i += TPB) {
        int d = i >> 9;       // / 512
        int k = i & 511;
        embT[k * DIMK + d] = embed[i];
    }
    __syncthreads();

    // Code norms from smem (one k per thread; TPB == NCODE)
    {
        int k = tid;
        const ulonglong2* e = (const ulonglong2*)(embT + k * DIMK);
        float s = 0.f;
#pragma unroll
        for (int j = 0; j < 16; j++) {
            ulonglong2 v = e[j];
            float a = lo2(v.x), b = hi2(v.x), c = lo2(v.y), d = hi2(v.y);
            s = fmaf(a, a, s); s = fmaf(b, b, s);
            s = fmaf(c, c, s); s = fmaf(d, d, s);
        }
        eNorm[k] = s;
    }
    __syncthreads();

    // Each thread owns one row, pre-scaled by -2 and packed into f32x2 regs.
    int n = blockIdx.x * TPB + tid;
    const float4* xr4 = (const float4*)(x + (size_t)n * DIMK);
    ull xp[DIMK / 2];
#pragma unroll
    for (int i = 0; i < DIMK / 4; i++) {
        float4 v = xr4[i];
        xp[2 * i + 0] = pack2(-2.f * v.x, -2.f * v.y);
        xp[2 * i + 1] = pack2(-2.f * v.z, -2.f * v.w);
    }

    float best = __int_as_float(0x7f800000);  // +inf
    int bi = 0;
    const float4* nrm4 = (const float4*)eNorm;
#pragma unroll 1
    for (int kb = 0; kb < NCODE / 4; kb++) {
        float4 nv = nrm4[kb];
        float nvv[4] = {nv.x, nv.y, nv.z, nv.w};
#pragma unroll
        for (int u = 0; u < 4; u++) {
            int k = kb * 4 + u;
            const ulonglong2* e = (const ulonglong2*)(embT + k * DIMK);
            ull a0 = 0, a1 = 0, a2 = 0, a3 = 0;
#pragma unroll
            for (int j = 0; j < 16; j += 2) {
                ulonglong2 ev0 = e[j];
                ulonglong2 ev1 = e[j + 1];
                fma2(a0, xp[2 * j + 0], ev0.x);
                fma2(a1, xp[2 * j + 1], ev0.y);
                fma2(a2, xp[2 * j + 2], ev1.x);
                fma2(a3, xp[2 * j + 3], ev1.y);
            }
            add2(a0, a0, a1);
            add2(a2, a2, a3);
            add2(a0, a0, a2);
            float s = (nvv[u] + lo2(a0)) + hi2(a0);  // ||e||^2 - 2 x.e
            if (s < best) { best = s; bi = k; }
        }
    }

    // Phase 2: cooperative, coalesced row writes + diff partial.
    int lane = tid & 31;
    int wbase = n - lane;
    float dsum = 0.f;
#pragma unroll 1
    for (int r = 0; r < 32; r++) {
        int bk = __shfl_sync(0xffffffffu, bi, r);
        float2 ev = ((const float2*)(embT + bk * DIMK))[lane];
        int rn = wbase + r;
        float2 xv = ((const float2*)(x + (size_t)rn * DIMK))[lane];
        ((float2*)(out + (size_t)rn * DIMK))[lane] = ev;
        float dx = ev.x - xv.x;
        float dy = ev.y - xv.y;
        dsum = fmaf(dx, dx, dsum);
        dsum = fmaf(dy, dy, dsum);
    }

    // embed_ind as float, if the output buffer carries it
    if (out_size >= NTOT + 1 + NROWS) {
        out[NTOT + 1 + n] = (float)bi;
    }

    // Deterministic per-block reduction of dsum (reuse smem; embT no longer read)
    __syncthreads();
    float* red = smem;
    red[tid] = dsum;
    __syncthreads();
#pragma unroll
    for (int s = TPB / 2; s > 0; s >>= 1) {
        if (tid < s) red[tid] += red[tid + s];
        __syncthreads();
    }

    // Exact fixed-point global accumulation (deterministic), last block finalizes
    if (tid == 0) {
        double bs = (double)red[0];
        unsigned long long q = (unsigned long long)(bs * 1048576.0 + 0.5);
        atomicAdd(&g_diff_acc, q);
        __threadfence();
        unsigned t = atomicAdd(&g_ticket, 1u);
        if (t == (unsigned)(NBLK - 1)) {
            unsigned long long tot = atomicExch(&g_diff_acc, 0ull);
            atomicExch(&g_ticket, 0u);
            if (out_size >= NTOT + 1) {
                out[NTOT] = (float)((double)tot * (1.0 / 1048576.0) / (double)NTOT);
            }
        }
    }
}

extern "C" void kernel_launch(void* const* d_in, const int* in_sizes, int n_in,
                              void* d_out, int out_size) {
    const float* x = (const float*)d_in[0];
    const float* embed = (const float*)d_in[1];
    float* out = (float*)d_out;

    int smem_bytes = (NCODE * DIMK + NCODE) * (int)sizeof(float);  // 133120
    cudaFuncSetAttribute(vq_kernel,
                         cudaFuncAttributeMaxDynamicSharedMemorySize, smem_bytes);

    vq_kernel<<<NBLK, TPB, smem_bytes>>>(x, embed, out, out_size);
}

// round 3
// speedup vs baseline: 1.3828x; 1.1459x over previous
#include <cuda_runtime.h>

// VQ quantize. x: [32,64,64,64] f32, embed: [64,512] f32.
// Output f32 packed: quantize (8388608) | diff (1) | embed_ind (131072).
// Register-blocked R=2 rows/thread to halve smem wavefront traffic.

#define DIMK 64
#define NCODE 512
#define NROWS (32 * 64 * 64)            // 131072
#define NTOT (NROWS * DIMK)             // 8388608
#define TPB 256
#define ROWS_PER_CTA (TPB * 2)          // 512
#define NBLK (NROWS / ROWS_PER_CTA)     // 256

__device__ unsigned long long g_diff_acc;  // zero-init; kernel restores to 0
__device__ unsigned int g_ticket;          // zero-init; kernel restores to 0

typedef unsigned long long ull;

__device__ __forceinline__ ull pack2(float a, float b) {
    ull r;
    asm("mov.b64 %0, {%1, %2};" : "=l"(r) : "f"(a), "f"(b));
    return r;
}
__device__ __forceinline__ float lo2(ull a) { return __uint_as_float((unsigned)(a & 0xffffffffull)); }
__device__ __forceinline__ float hi2(ull a) { return __uint_as_float((unsigned)(a >> 32)); }

__device__ __forceinline__ void fma2(ull& acc, ull a, ull b) {
    asm("fma.rn.f32x2 %0, %1, %2, %3;" : "=l"(acc) : "l"(a), "l"(b), "l"(acc));
}
__device__ __forceinline__ void add2(ull& d, ull a, ull b) {
    asm("add.rn.f32x2 %0, %1, %2;" : "=l"(d) : "l"(a), "l"(b));
}

// smem: embT [512][64] floats (codebook transposed), then eNorm[512]
__global__ __launch_bounds__(TPB, 1)
void vq_kernel(const float* __restrict__ x,
               const float* __restrict__ embed,
               float* __restrict__ out,
               int out_size) {
    extern __shared__ float smem[];
    float* embT = smem;                  // [k*64 + d]
    float* eNorm = smem + NCODE * DIMK;  // [k]
    int tid = threadIdx.x;

    // Load codebook transposed: embed[d*512+k] -> embT[k*64+d] (coalesced gmem)
    for (int i = tid; i < NCODE * DIMK; i += TPB) {
        int d = i >> 9;       // / 512
        int k = i & 511;
        embT[k * DIMK + d] = embed[i];
    }
    __syncthreads();

    // Code norms from smem (two k per thread)
    for (int k = tid; k < NCODE; k += TPB) {
        const ulonglong2* e = (const ulonglong2*)(embT + k * DIMK);
        float s = 0.f;
#pragma unroll
        for (int j = 0; j < 16; j++) {
            ulonglong2 v = e[j];
            float a = lo2(v.x), b = hi2(v.x), c = lo2(v.y), d = hi2(v.y);
            s = fmaf(a, a, s); s = fmaf(b, b, s);
            s = fmaf(c, c, s); s = fmaf(d, d, s);
        }
        eNorm[k] = s;
    }
    __syncthreads();

    // Two rows per thread, pre-scaled by -2, packed f32x2 in registers.
    int base = blockIdx.x * ROWS_PER_CTA;
    int n0 = base + tid;
    int n1 = base + TPB + tid;
    ull xp0[DIMK / 2], xp1[DIMK / 2];
    {
        const float4* r0 = (const float4*)(x + (size_t)n0 * DIMK);
        const float4* r1 = (const float4*)(x + (size_t)n1 * DIMK);
#pragma unroll
        for (int i = 0; i < DIMK / 4; i++) {
            float4 a = r0[i];
            xp0[2 * i + 0] = pack2(-2.f * a.x, -2.f * a.y);
            xp0[2 * i + 1] = pack2(-2.f * a.z, -2.f * a.w);
            float4 b = r1[i];
            xp1[2 * i + 0] = pack2(-2.f * b.x, -2.f * b.y);
            xp1[2 * i + 1] = pack2(-2.f * b.z, -2.f * b.w);
        }
    }

    float best0 = __int_as_float(0x7f800000), best1 = best0;
    int bi0 = 0, bi1 = 0;
    const float4* nrm4 = (const float4*)eNorm;
#pragma unroll 1
    for (int kb = 0; kb < NCODE / 4; kb++) {
        float4 nv = nrm4[kb];
        float nvv[4] = {nv.x, nv.y, nv.z, nv.w};
#pragma unroll
        for (int u = 0; u < 4; u++) {
            int k = kb * 4 + u;
            const ulonglong2* e = (const ulonglong2*)(embT + k * DIMK);
            ull p0 = 0, p1 = 0, p2 = 0, p3 = 0;   // row0 accumulators
            ull q0 = 0, q1 = 0, q2 = 0, q3 = 0;   // row1 accumulators
#pragma unroll
            for (int j = 0; j < 16; j += 2) {
                ulonglong2 ev0 = e[j];
                ulonglong2 ev1 = e[j + 1];
                fma2(p0, xp0[2 * j + 0], ev0.x);
                fma2(q0, xp1[2 * j + 0], ev0.x);
                fma2(p1, xp0[2 * j + 1], ev0.y);
                fma2(q1, xp1[2 * j + 1], ev0.y);
                fma2(p2, xp0[2 * j + 2], ev1.x);
                fma2(q2, xp1[2 * j + 2], ev1.x);
                fma2(p3, xp0[2 * j + 3], ev1.y);
                fma2(q3, xp1[2 * j + 3], ev1.y);
            }
            add2(p0, p0, p1); add2(p2, p2, p3); add2(p0, p0, p2);
            add2(q0, q0, q1); add2(q2, q2, q3); add2(q0, q0, q2);
            float s0 = (nvv[u] + lo2(p0)) + hi2(p0);
            float s1 = (nvv[u] + lo2(q0)) + hi2(q0);
            if (s0 < best0) { best0 = s0; bi0 = k; }
            if (s1 < best1) { best1 = s1; bi1 = k; }
        }
    }

    // Phase 2: cooperative, coalesced row writes + diff partial.
    int lane = tid & 31;
    float dsum = 0.f;
#pragma unroll 1
    for (int half = 0; half < 2; half++) {
        int myn = half ? n1 : n0;
        int mybi = half ? bi1 : bi0;
        int wbase = myn - lane;
#pragma unroll 1
        for (int r = 0; r < 32; r++) {
            int bk = __shfl_sync(0xffffffffu, mybi, r);
            float2 ev = ((const float2*)(embT + bk * DIMK))[lane];
            int rn = wbase + r;
            float2 xv = ((const float2*)(x + (size_t)rn * DIMK))[lane];
            ((float2*)(out + (size_t)rn * DIMK))[lane] = ev;
            float dx = ev.x - xv.x;
            float dy = ev.y - xv.y;
            dsum = fmaf(dx, dx, dsum);
            dsum = fmaf(dy, dy, dsum);
        }
    }

    // embed_ind as float, if the output buffer carries it
    if (out_size >= NTOT + 1 + NROWS) {
        out[NTOT + 1 + n0] = (float)bi0;
        out[NTOT + 1 + n1] = (float)bi1;
    }

    // Deterministic per-block reduction of dsum (reuse smem)
    __syncthreads();
    float* red = smem;
    red[tid] = dsum;
    __syncthreads();
#pragma unroll
    for (int s = TPB / 2; s > 0; s >>= 1) {
        if (tid < s) red[tid] += red[tid + s];
        __syncthreads();
    }

    // Exact fixed-point global accumulation (deterministic), last block finalizes
    if (tid == 0) {
        double bs = (double)red[0];
        unsigned long long q = (unsigned long long)(bs * 1048576.0 + 0.5);
        atomicAdd(&g_diff_acc, q);
        __threadfence();
        unsigned t = atomicAdd(&g_ticket, 1u);
        if (t == (unsigned)(NBLK - 1)) {
            unsigned long long tot = atomicExch(&g_diff_acc, 0ull);
            atomicExch(&g_ticket, 0u);
            if (out_size >= NTOT + 1) {
                out[NTOT] = (float)((double)tot * (1.0 / 1048576.0) / (double)NTOT);
            }
        }
    }
}

extern "C" void kernel_launch(void* const* d_in, const int* in_sizes, int n_in,
                              void* d_out, int out_size) {
    const float* x = (const float*)d_in[0];
    const float* embed = (const float*)d_in[1];
    float* out = (float*)d_out;

    int smem_bytes = (NCODE * DIMK + NCODE) * (int)sizeof(float);  // 133120
    cudaFuncSetAttribute(vq_kernel,
                         cudaFuncAttributeMaxDynamicSharedMemorySize, smem_bytes);

    vq_kernel<<<NBLK, TPB, smem_bytes>>>(x, embed, out, out_size);
}

// round 5
// speedup vs baseline: 2.0682x; 1.4956x over previous
#include <cuda_runtime.h>
#include <cstdint>

// VQ quantize via mma.sync tf32 (3xTF32 split = fp32-grade scores).
// x: [131072, 64] f32, embed: [64, 512] f32.
// Out f32: quantize (8388608) | diff (1) | embed_ind (131072).

#define DIMK 64
#define NCODE 512
#define NROWS (32 * 64 * 64)
#define NTOT (NROWS * DIMK)
#define TPB 256
#define M_TILE 256
#define NBLK (NROWS / M_TILE)   // 512
#define XS_STRIDE 68            // padded row stride (floats) -> conflict-free frag build

// smem byte offsets
#define SM_XS 0                         // 256*68*4 = 69632
#define SM_B 69632                      // 131072 (half of B fragments)
#define SM_NRM (SM_B + 131072)          // 2048
#define SM_WIN (SM_NRM + 2048)          // 1024
#define SM_RED (SM_WIN + 1024)          // 1024
#define SM_BYTES (SM_RED + 1024)        // 204800

__device__ __align__(16) float4 g_Bfrag[64 * 8 * 32];   // 256KB: [nc][kc][lane] = {bh0,bh1,bl0,bl1}
__device__ __align__(16) float g_embT[NCODE * DIMK];    // fp32 codes [k][d]
__device__ float g_nrm[NCODE];
__device__ unsigned long long g_diff_acc;   // zero-init; restored each run
__device__ unsigned int g_ticket;

__device__ __forceinline__ uint32_t tf32_hi(float f) {
    uint32_t r;
    asm("cvt.rna.tf32.f32 %0, %1;" : "=r"(r) : "f"(f));
    return r;
}
__device__ __forceinline__ void mma8(float* c, const uint32_t* a, uint32_t b0, uint32_t b1) {
    asm volatile(
        "mma.sync.aligned.m16n8k8.row.col.f32.tf32.tf32.f32 "
        "{%0,%1,%2,%3}, {%4,%5,%6,%7}, {%8,%9}, {%0,%1,%2,%3};"
        : "+f"(c[0]), "+f"(c[1]), "+f"(c[2]), "+f"(c[3])
        : "r"(a[0]), "r"(a[1]), "r"(a[2]), "r"(a[3]), "r"(b0), "r"(b1));
}

// ---- prep: codebook transpose, norms, B fragments in mma layout ----
__global__ void vq_prep(const float* __restrict__ embed) {
    int t = threadIdx.x;  // 512
    float nr = 0.f;
    for (int d = 0; d < DIMK; d++) {
        float e = embed[d * NCODE + t];
        g_embT[t * DIMK + d] = e;
        nr = fmaf(e, e, nr);
    }
    g_nrm[t] = nr;
    // B fragment: for mma.m16n8k8 col-major B: b0=B[tig][gid], b1=B[tig+4][gid]
    for (int i = t; i < 64 * 8 * 32; i += 512) {
        int lane = i & 31;
        int kc = (i >> 5) & 7;
        int nc = i >> 8;
        int gid = lane >> 2, tig = lane & 3;
        int n = nc * 8 + gid;
        int k0 = kc * 8 + tig;
        float v0 = -2.f * embed[k0 * NCODE + n];
        float v1 = -2.f * embed[(k0 + 4) * NCODE + n];
        uint32_t h0 = tf32_hi(v0), h1 = tf32_hi(v1);
        uint32_t l0 = tf32_hi(v0 - __uint_as_float(h0));
        uint32_t l1 = tf32_hi(v1 - __uint_as_float(h1));
        float4 f;
        f.x = __uint_as_float(h0);
        f.y = __uint_as_float(h1);
        f.z = __uint_as_float(l0);
        f.w = __uint_as_float(l1);
        g_Bfrag[i] = f;
    }
}

__global__ __launch_bounds__(TPB, 1)
void vq_mma_kernel(const float* __restrict__ x,
                   float* __restrict__ out,
                   int out_size) {
    extern __shared__ char smem[];
    float* xs = (float*)(smem + SM_XS);
    float4* Bsm = (float4*)(smem + SM_B);
    float* nsm = (float*)(smem + SM_NRM);
    int* WIN = (int*)(smem + SM_WIN);
    float* red = (float*)(smem + SM_RED);

    int tid = threadIdx.x, wid = tid >> 5, lane = tid & 31;
    int gid = lane >> 2, tig = lane & 3;
    int base_row = blockIdx.x * M_TILE;

    // x tile -> padded smem (coalesced float4)
    for (int i = tid; i < M_TILE * 16; i += TPB) {
        int r = i >> 4, c4 = i & 15;
        float4 v = ((const float4*)(x + (size_t)(base_row + r) * DIMK))[c4];
        float* dst = xs + r * XS_STRIDE + c4 * 4;
        dst[0] = v.x; dst[1] = v.y; dst[2] = v.z; dst[3] = v.w;
    }
    for (int i = tid; i < NCODE; i += TPB) nsm[i] = g_nrm[i];
    __syncthreads();

    // A fragments (tf32 hi/lo) in registers: 2 m16 tiles x 8 k-chunks
    int m0 = wid * 32;
    uint32_t Ah[2][8][4], Al[2][8][4];
#pragma unroll
    for (int t2 = 0; t2 < 2; t2++)
#pragma unroll
        for (int kc = 0; kc < 8; kc++) {
            int r0 = m0 + t2 * 16 + gid;
            int c0 = kc * 8 + tig;
            float f[4];
            f[0] = xs[r0 * XS_STRIDE + c0];             // a0: row gid,   col tig
            f[1] = xs[(r0 + 8) * XS_STRIDE + c0];       // a1: row gid+8, col tig
            f[2] = xs[r0 * XS_STRIDE + c0 + 4];         // a2: row gid,   col tig+4
            f[3] = xs[(r0 + 8) * XS_STRIDE + c0 + 4];   // a3: row gid+8, col tig+4
#pragma unroll
            for (int j = 0; j < 4; j++) {
                uint32_t h = tf32_hi(f[j]);
                Ah[t2][kc][j] = h;
                Al[t2][kc][j] = tf32_hi(f[j] - __uint_as_float(h));
            }
        }

    float best[4];
    int bi[4];
#pragma unroll
    for (int j = 0; j < 4; j++) { best[j] = __int_as_float(0x7f800000); bi[j] = 0; }

#pragma unroll 1
    for (int half = 0; half < 2; half++) {
        __syncthreads();  // previous half's readers done before overwrite
        // load this half's B fragments: 8192 float4 coalesced
        const float4* src = g_Bfrag + half * 8192;
        for (int i = tid; i < 8192; i += TPB) Bsm[i] = src[i];
        __syncthreads();

#pragma unroll 1
        for (int nc = 0; nc < 32; nc++) {
            float acc0[4] = {0.f, 0.f, 0.f, 0.f};
            float acc1[4] = {0.f, 0.f, 0.f, 0.f};
#pragma unroll
            for (int kc = 0; kc < 8; kc++) {
                float4 b = Bsm[(nc * 8 + kc) * 32 + lane];
                uint32_t bh0 = __float_as_uint(b.x), bh1 = __float_as_uint(b.y);
                uint32_t bl0 = __float_as_uint(b.z), bl1 = __float_as_uint(b.w);
                mma8(acc0, Ah[0][kc], bh0, bh1);
                mma8(acc0, Al[0][kc], bh0, bh1);
                mma8(acc0, Ah[0][kc], bl0, bl1);
                mma8(acc1, Ah[1][kc], bh0, bh1);
                mma8(acc1, Al[1][kc], bh0, bh1);
                mma8(acc1, Ah[1][kc], bl0, bl1);
            }
            int n0 = half * 256 + nc * 8;
            float2 nv = *(const float2*)(nsm + n0 + 2 * tig);
            int ca = n0 + 2 * tig, cb = ca + 1;
            // rows: j0=gid (acc0 c0/c1), j1=gid+8 (acc0 c2/c3), j2=gid+16, j3=gid+24
            float s;
            s = acc0[0] + nv.x; if (s < best[0]) { best[0] = s; bi[0] = ca; }
            s = acc0[1] + nv.y; if (s < best[0]) { best[0] = s; bi[0] = cb; }
            s = acc0[2] + nv.x; if (s < best[1]) { best[1] = s; bi[1] = ca; }
            s = acc0[3] + nv.y; if (s < best[1]) { best[1] = s; bi[1] = cb; }
            s = acc1[0] + nv.x; if (s < best[2]) { best[2] = s; bi[2] = ca; }
            s = acc1[1] + nv.y; if (s < best[2]) { best[2] = s; bi[2] = cb; }
            s = acc1[2] + nv.x; if (s < best[3]) { best[3] = s; bi[3] = ca; }
            s = acc1[3] + nv.y; if (s < best[3]) { best[3] = s; bi[3] = cb; }
        }
    }

    // reduce across the 4 lanes of each quad (they share rows, cover different n)
#pragma unroll
    for (int j = 0; j < 4; j++) {
        float b = best[j];
        int ix = bi[j];
#pragma unroll
        for (int o = 1; o < 4; o <<= 1) {
            float ob = __shfl_xor_sync(0xffffffffu, b, o);
            int oi = __shfl_xor_sync(0xffffffffu, ix, o);
            if (ob < b || (ob == b && oi < ix)) { b = ob; ix = oi; }
        }
        if (tig == 0) WIN[m0 + j * 8 + gid] = ix;
    }
    __syncthreads();

    // phase 2: quantize writes + diff + ind (32 rows per warp)
    float dsum = 0.f;
    bool write_ind = (out_size >= NTOT + 1 + NROWS);
#pragma unroll 1
    for (int i = 0; i < 32; i++) {
        int r = wid * 32 + i;
        int bk = WIN[r];
        size_t n = (size_t)base_row + r;
        float2 ev = ((const float2*)(g_embT + bk * DIMK))[lane];
        float2 xv = ((const float2*)(x + n * DIMK))[lane];
        ((float2*)(out + n * DIMK))[lane] = ev;
        float dx = ev.x - xv.x, dy = ev.y - xv.y;
        dsum = fmaf(dx, dx, dsum);
        dsum = fmaf(dy, dy, dsum);
        if (lane == 0 && write_ind) out[NTOT + 1 + n] = (float)bk;
    }

    // deterministic block reduce + fixed-point global accumulate
    red[tid] = dsum;
    __syncthreads();
#pragma unroll
    for (int s = TPB / 2; s > 0; s >>= 1) {
        if (tid < s) red[tid] += red[tid + s];
        __syncthreads();
    }
    if (tid == 0) {
        unsigned long long q = (unsigned long long)((double)red[0] * 1048576.0 + 0.5);
        atomicAdd(&g_diff_acc, q);
        __threadfence();
        unsigned t = atomicAdd(&g_ticket, 1u);
        if (t == (unsigned)(NBLK - 1)) {
            unsigned long long tot = atomicExch(&g_diff_acc, 0ull);
            atomicExch(&g_ticket, 0u);
            if (out_size >= NTOT + 1)
                out[NTOT] = (float)((double)tot * (1.0 / 1048576.0) / (double)NTOT);
        }
    }
}

extern "C" void kernel_launch(void* const* d_in, const int* in_sizes, int n_in,
                              void* d_out, int out_size) {
    const float* x = (const float*)d_in[0];
    const float* embed = (const float*)d_in[1];
    float* out = (float*)d_out;

    cudaFuncSetAttribute(vq_mma_kernel,
                         cudaFuncAttributeMaxDynamicSharedMemorySize, SM_BYTES);

    vq_prep<<<1, NCODE>>>(embed);
    vq_mma_kernel<<<NBLK, TPB, SM_BYTES>>>(x, out, out_size);
}